// round 1
// baseline (speedup 1.0000x reference)
#include <cuda_runtime.h>
#include <cuda_bf16.h>

#define HLR 128
#define WLR 128
#define HH 512
#define WH 512
#define CC 64
#define NPIX (HH*WH)      // 262144
#define NQ 262144

// ---- scratch (device globals: allocation-free) ----
__device__ float g_feat[CC*HLR*WLR];     // 4 MB  [c][y][x]
__device__ float g_hidden[CC*HH*WH];     // 64 MB [c][y][x]
__device__ float g_pred[3*HH*WH];        // 3 MB  [c][y][x]
__device__ float g_off[16*2];
__device__ float g_r[16*4];
__device__ float g_A[16*512];            // [ph][c][k]  (64x8)
__device__ float g_B[16*512];            // [ph][k][c]  (8x64)

// ---------------- Kernel 1: encoder conv3x3 (3 -> 64, 128x128, pad 1) ----------------
__global__ void enc_conv(const float* __restrict__ inp,
                         const float* __restrict__ w,
                         const float* __restrict__ b) {
    int t = blockIdx.x*blockDim.x + threadIdx.x;   // c*16384 + y*128 + x
    if (t >= CC*HLR*WLR) return;
    int x = t & (WLR-1);
    int y = (t >> 7) & (HLR-1);
    int c = t >> 14;
    float acc = __ldg(&b[c]);
    #pragma unroll
    for (int ci = 0; ci < 3; ci++) {
        #pragma unroll
        for (int ky = 0; ky < 3; ky++) {
            int yy = y + ky - 1;
            if ((unsigned)yy >= (unsigned)HLR) continue;
            #pragma unroll
            for (int kx = 0; kx < 3; kx++) {
                int xx = x + kx - 1;
                if ((unsigned)xx >= (unsigned)WLR) continue;
                acc = fmaf(__ldg(&inp[(ci*HLR + yy)*WLR + xx]),
                           __ldg(&w[((c*3 + ci)*3 + ky)*3 + kx]), acc);
            }
        }
    }
    g_feat[t] = acc;
}

// ---------------- Kernel 2: phase MLP (16 phases only) ----------------
__global__ void phase_mlp(const float* __restrict__ w1, const float* __restrict__ b1,
                          const float* __restrict__ w2, const float* __restrict__ b2,
                          const float* __restrict__ rw, const float* __restrict__ rb,
                          const float* __restrict__ ow, const float* __restrict__ ob) {
    int t = threadIdx.x;
    if (t >= 16) return;
    int py = t >> 2, px = t & 3;
    float ch = (py + 0.5f)/4.0f; ch = ch - floorf(ch + 0.001f) - 0.5f;
    float cw = (px + 0.5f)/4.0f; cw = cw - floorf(cw + 0.001f) - 0.5f;
    const float cs = 0.25f;
    float e1[64];
    #pragma unroll
    for (int c = 0; c < 64; c++) {
        float s = __ldg(&b1[c]);
        s = fmaf(__ldg(&w1[c*4+0]), cs, s);
        s = fmaf(__ldg(&w1[c*4+1]), cs, s);
        s = fmaf(__ldg(&w1[c*4+2]), ch, s);
        s = fmaf(__ldg(&w1[c*4+3]), cw, s);
        e1[c] = fmaxf(s, 0.0f);
    }
    float aO0 = __ldg(&ob[0]), aO1 = __ldg(&ob[1]);
    float aR0 = __ldg(&rb[0]), aR1 = __ldg(&rb[1]), aR2 = __ldg(&rb[2]), aR3 = __ldg(&rb[3]);
    for (int c = 0; c < 64; c++) {
        float s = __ldg(&b2[c]);
        #pragma unroll
        for (int j = 0; j < 64; j++) s = fmaf(__ldg(&w2[c*64+j]), e1[j], s);
        s = fmaxf(s, 0.0f);
        aO0 = fmaf(__ldg(&ow[c]),      s, aO0);
        aO1 = fmaf(__ldg(&ow[64+c]),   s, aO1);
        aR0 = fmaf(__ldg(&rw[c]),      s, aR0);
        aR1 = fmaf(__ldg(&rw[64+c]),   s, aR1);
        aR2 = fmaf(__ldg(&rw[128+c]),  s, aR2);
        aR3 = fmaf(__ldg(&rw[192+c]),  s, aR3);
    }
    g_off[t*2+0] = aO0;
    g_off[t*2+1] = aO1;
    g_r[t*4+0] = 1.0f/(1.0f + expf(-aR0));
    g_r[t*4+1] = 1.0f/(1.0f + expf(-aR1));
    g_r[t*4+2] = 1.0f/(1.0f + expf(-aR2));
    g_r[t*4+3] = 1.0f/(1.0f + expf(-aR3));
}

// ---------------- Kernel 3: build A(r), B(r) per phase ----------------
__global__ void build_ab(const float* __restrict__ wc, const float* __restrict__ we) {
    int t = blockIdx.x*blockDim.x + threadIdx.x;   // 16384 threads
    if (t < 8192) {
        int ph = t >> 9, rem = t & 511;
        int c = rem >> 3, k = rem & 7;
        float s = 0.0f;
        #pragma unroll
        for (int e = 0; e < 4; e++)
            s = fmaf(g_r[ph*4+e], __ldg(&we[(e*64 + c)*8 + k]), s);
        g_A[ph*512 + c*8 + k] = s;
    } else {
        int u = t - 8192;
        int ph = u >> 9, rem = u & 511;
        int k = rem >> 6, c = rem & 63;
        float s = 0.0f;
        #pragma unroll
        for (int e = 0; e < 4; e++)
            s = fmaf(g_r[ph*4+e], __ldg(&wc[(e*8 + k)*64 + c]), s);
        g_B[ph*512 + k*64 + c] = s;
    }
}

// ---------------- Kernel 4: fused grid-sample + expert mixing ----------------
#define PHSTR 520   // padded per-phase stride (floats): 520 % 32 == 8 -> conflict-free
__global__ void __launch_bounds__(256)
main_fused() {
    __shared__ float sA[4*PHSTR];
    __shared__ float sB[4*PHSTR];
    __shared__ float s_off[8];

    int p0 = blockIdx.x * 256;
    int py4 = (p0 >> 9) & 3;                 // y & 3 (same for whole block)
    for (int i = threadIdx.x; i < 4*512; i += 256) {
        int phl = i >> 9, ii = i & 511;
        sA[phl*PHSTR + ii] = g_A[(py4*4 + phl)*512 + ii];
        sB[phl*PHSTR + ii] = g_B[(py4*4 + phl)*512 + ii];
    }
    if (threadIdx.x < 8) s_off[threadIdx.x] = g_off[py4*8 + threadIdx.x];
    __syncthreads();

    int p = p0 + threadIdx.x;
    int x = p & 511, y = p >> 9;
    int phl = x & 3;
    float off0 = s_off[phl*2+0];
    float off1 = s_off[phl*2+1];

    float gx = ((x + 0.5f)/4.0f - 0.5f)*2.0f/127.0f - 1.0f + off0*2.0f/127.0f;
    float gy = ((y + 0.5f)/4.0f - 0.5f)*2.0f/127.0f - 1.0f + off1*2.0f/127.0f;
    float xs = (gx + 1.0f)*0.5f*127.0f;
    float ys = (gy + 1.0f)*0.5f*127.0f;
    float x0f = floorf(xs), y0f = floorf(ys);
    float wx1 = xs - x0f, wx0 = 1.0f - wx1;
    float wy1 = ys - y0f, wy0 = 1.0f - wy1;
    int x0 = (int)x0f, y0 = (int)y0f;
    int x1 = x0 + 1, y1 = y0 + 1;
    float mx0 = ((unsigned)x0 < 128u) ? 1.0f : 0.0f;
    float mx1 = ((unsigned)x1 < 128u) ? 1.0f : 0.0f;
    float my0 = ((unsigned)y0 < 128u) ? 1.0f : 0.0f;
    float my1 = ((unsigned)y1 < 128u) ? 1.0f : 0.0f;
    float w00 = wy0*wx0*my0*mx0;
    float w01 = wy0*wx1*my0*mx1;
    float w10 = wy1*wx0*my1*mx0;
    float w11 = wy1*wx1*my1*mx1;
    int xc0 = min(max(x0,0),127), xc1 = min(max(x1,0),127);
    int yc0 = min(max(y0,0),127), yc1 = min(max(y1,0),127);
    int i00 = yc0*128 + xc0, i01 = yc0*128 + xc1;
    int i10 = yc1*128 + xc0, i11 = yc1*128 + xc1;

    float fea0[64];
    #pragma unroll
    for (int c = 0; c < 64; c++) {
        const float* fc = g_feat + c*16384;
        float v =      __ldg(fc + i00) * w00;
        v = fmaf(__ldg(fc + i01), w01, v);
        v = fmaf(__ldg(fc + i10), w10, v);
        v = fmaf(__ldg(fc + i11), w11, v);
        fea0[c] = v;
    }

    // mid = B(ph) * fea0   (8x64)
    float mid[8];
    const float4* B4 = (const float4*)(sB + phl*PHSTR);
    #pragma unroll
    for (int k = 0; k < 8; k++) {
        float s = 0.0f;
        #pragma unroll
        for (int j = 0; j < 16; j++) {
            float4 v = B4[k*16 + j];
            s = fmaf(v.x, fea0[4*j+0], s);
            s = fmaf(v.y, fea0[4*j+1], s);
            s = fmaf(v.z, fea0[4*j+2], s);
            s = fmaf(v.w, fea0[4*j+3], s);
        }
        mid[k] = s;
    }

    // hidden = fea0 + A(ph) * mid   (64x8)
    float* hp = g_hidden + p;
    #pragma unroll
    for (int c = 0; c < 64; c++) {
        const float4* A4 = (const float4*)(sA + phl*PHSTR + c*8);
        float4 a0 = A4[0], a1 = A4[1];
        float s = fea0[c];
        s = fmaf(a0.x, mid[0], s);
        s = fmaf(a0.y, mid[1], s);
        s = fmaf(a0.z, mid[2], s);
        s = fmaf(a0.w, mid[3], s);
        s = fmaf(a1.x, mid[4], s);
        s = fmaf(a1.y, mid[5], s);
        s = fmaf(a1.z, mid[6], s);
        s = fmaf(a1.w, mid[7], s);
        hp[c << 18] = s;
    }
}

// ---------------- Kernel 5: tail conv3x3 (64 -> 3, 512x512, pad 1) ----------------
__global__ void __launch_bounds__(256)
tail_conv(const float* __restrict__ tw, const float* __restrict__ tb) {
    __shared__ float sw2[64*3*12];   // [c][o][12] (9 used, padded for float4)
    for (int j = threadIdx.x; j < 64*3*12; j += 256) {
        int c = j / 36, o = (j % 36) / 12, k = j % 12;
        sw2[j] = (k < 9) ? __ldg(&tw[(o*64 + c)*9 + k]) : 0.0f;
    }
    __syncthreads();

    int t = blockIdx.x*blockDim.x + threadIdx.x;  // 65536: 512 rows x 128 x-groups
    int x0 = (t & 127) << 2;
    int y  = t >> 7;

    float acc[3][4];
    float b0 = __ldg(&tb[0]), b1 = __ldg(&tb[1]), b2 = __ldg(&tb[2]);
    #pragma unroll
    for (int px = 0; px < 4; px++) { acc[0][px] = b0; acc[1][px] = b1; acc[2][px] = b2; }

    for (int c = 0; c < 64; c++) {
        const float* hc = g_hidden + (c << 18);
        float v[3][6];
        #pragma unroll
        for (int r = 0; r < 3; r++) {
            int yy = y + r - 1;
            const float* rp = hc + yy*512;
            bool ry = ((unsigned)yy < 512u);
            #pragma unroll
            for (int j = 0; j < 6; j++) {
                int xx = x0 + j - 1;
                v[r][j] = (ry && ((unsigned)xx < 512u)) ? __ldg(rp + xx) : 0.0f;
            }
        }
        #pragma unroll
        for (int o = 0; o < 3; o++) {
            const float* wp = &sw2[(c*3 + o)*12];
            float4 wa = *(const float4*)wp;
            float4 wb = *(const float4*)(wp + 4);
            float  w8 = wp[8];
            #pragma unroll
            for (int px = 0; px < 4; px++) {
                float s = acc[o][px];
                s = fmaf(v[0][px+0], wa.x, s);
                s = fmaf(v[0][px+1], wa.y, s);
                s = fmaf(v[0][px+2], wa.z, s);
                s = fmaf(v[1][px+0], wa.w, s);
                s = fmaf(v[1][px+1], wb.x, s);
                s = fmaf(v[1][px+2], wb.y, s);
                s = fmaf(v[2][px+0], wb.z, s);
                s = fmaf(v[2][px+1], wb.w, s);
                s = fmaf(v[2][px+2], w8,   s);
                acc[o][px] = s;
            }
        }
    }
    int base = (y << 9) + x0;
    #pragma unroll
    for (int o = 0; o < 3; o++)
        #pragma unroll
        for (int px = 0; px < 4; px++)
            g_pred[(o << 18) + base + px] = acc[o][px];
}

// ---------------- Kernel 6: query gather (nearest, round-half-even) ----------------
__global__ void gather_q(const float* __restrict__ coord,
                         const float* __restrict__ cell,
                         float* __restrict__ out) {
    int q = blockIdx.x*blockDim.x + threadIdx.x;
    if (q >= NQ) return;
    float cy = __ldg(&coord[q*2+0]);
    float cx = __ldg(&coord[q*2+1]);
    float ly = __ldg(&cell[q*2+0]);
    float lx = __ldg(&cell[q*2+1]);
    float gyq = fminf(fmaxf(cy - ly*0.5f + 1e-6f, -1.0f + 1e-6f), 1.0f - 1e-6f);
    float gxq = fminf(fmaxf(cx - lx*0.5f + 1e-6f, -1.0f + 1e-6f), 1.0f - 1e-6f);
    int xi = (int)rintf((gxq + 1.0f)*0.5f*511.0f);
    int yi = (int)rintf((gyq + 1.0f)*0.5f*511.0f);
    xi = min(max(xi,0),511);
    yi = min(max(yi,0),511);
    int idx = (yi << 9) + xi;
    out[q*3+0] = g_pred[idx];
    out[q*3+1] = g_pred[(1 << 18) + idx];
    out[q*3+2] = g_pred[(2 << 18) + idx];
}

extern "C" void kernel_launch(void* const* d_in, const int* in_sizes, int n_in,
                              void* d_out, int out_size) {
    const float* inp    = (const float*)d_in[0];
    const float* coord  = (const float*)d_in[1];
    const float* cell   = (const float*)d_in[2];
    const float* enc_w  = (const float*)d_in[3];
    const float* enc_b  = (const float*)d_in[4];
    const float* body_w1= (const float*)d_in[5];
    const float* body_b1= (const float*)d_in[6];
    const float* body_w2= (const float*)d_in[7];
    const float* body_b2= (const float*)d_in[8];
    const float* rout_w = (const float*)d_in[9];
    const float* rout_b = (const float*)d_in[10];
    const float* off_w  = (const float*)d_in[11];
    const float* off_b  = (const float*)d_in[12];
    const float* tail_w = (const float*)d_in[13];
    const float* tail_b = (const float*)d_in[14];
    const float* wcmp   = (const float*)d_in[15];
    const float* wexp   = (const float*)d_in[16];
    float* out = (float*)d_out;

    enc_conv<<<4096, 256>>>(inp, enc_w, enc_b);
    phase_mlp<<<1, 32>>>(body_w1, body_b1, body_w2, body_b2,
                         rout_w, rout_b, off_w, off_b);
    build_ab<<<32, 512>>>(wcmp, wexp);
    main_fused<<<1024, 256>>>();
    tail_conv<<<256, 256>>>(tail_w, tail_b);
    gather_q<<<1024, 256>>>(coord, cell, out);
}

// round 2
// speedup vs baseline: 1.2919x; 1.2919x over previous
#include <cuda_runtime.h>
#include <cuda_bf16.h>

#define HLR 128
#define WLR 128
#define HH 512
#define WH 512
#define CC 64
#define NPIX (HH*WH)      // 262144
#define NQ 262144

// ---- scratch (device globals: allocation-free) ----
__device__ __align__(16) float g_feat[NPIX/16*CC];   // 4 MB, channel-LAST [y*128+x][c]
__device__ __align__(16) float g_hidden[CC*NPIX];    // 64 MB, channel-FIRST [c][y][x]
__device__ __align__(16) float g_pred[3*NPIX];       // 3 MB  [o][y][x]
__device__ float g_off[16*2];
__device__ float g_r[16*4];
__device__ float g_A[16*512];            // [ph][c][k]  (64x8)
__device__ float g_B[16*512];            // [ph][k][c]  (8x64)

// ---------------- Kernel 1: encoder conv3x3 (3 -> 64, 128x128) -> channel-last ----------------
__global__ void __launch_bounds__(128)
enc_conv(const float* __restrict__ inp,
         const float* __restrict__ w,
         const float* __restrict__ b) {
    __shared__ float sw[27*64];   // [j][c]
    __shared__ float sb[64];
    for (int idx = threadIdx.x; idx < 27*64; idx += 128) {
        int j = idx >> 6, c = idx & 63;
        sw[idx] = __ldg(&w[c*27 + j]);
    }
    if (threadIdx.x < 64) sb[threadIdx.x] = __ldg(&b[threadIdx.x]);
    __syncthreads();

    int t = blockIdx.x*128 + threadIdx.x;   // pixel
    int x = t & 127, y = t >> 7;

    float in[27];
    #pragma unroll
    for (int ci = 0; ci < 3; ci++)
        #pragma unroll
        for (int ky = 0; ky < 3; ky++) {
            int yy = y + ky - 1;
            bool ry = ((unsigned)yy < 128u);
            #pragma unroll
            for (int kx = 0; kx < 3; kx++) {
                int xx = x + kx - 1;
                in[ci*9 + ky*3 + kx] = (ry && ((unsigned)xx < 128u))
                    ? __ldg(&inp[(ci*128 + yy)*128 + xx]) : 0.0f;
            }
        }

    float4* F = (float4*)g_feat;
    #pragma unroll
    for (int c4 = 0; c4 < 16; c4++) {
        float4 acc = make_float4(sb[c4*4+0], sb[c4*4+1], sb[c4*4+2], sb[c4*4+3]);
        #pragma unroll
        for (int j = 0; j < 27; j++) {
            float fin = in[j];
            const float4 wv = *(const float4*)&sw[j*64 + c4*4];
            acc.x = fmaf(fin, wv.x, acc.x);
            acc.y = fmaf(fin, wv.y, acc.y);
            acc.z = fmaf(fin, wv.z, acc.z);
            acc.w = fmaf(fin, wv.w, acc.w);
        }
        F[t*16 + c4] = acc;
    }
}

// ---------------- Kernel 2: phase MLP, parallel (1 block, 1024 threads) ----------------
__global__ void __launch_bounds__(1024)
phase_mlp(const float* __restrict__ w1, const float* __restrict__ b1,
          const float* __restrict__ w2, const float* __restrict__ b2,
          const float* __restrict__ rw, const float* __restrict__ rb,
          const float* __restrict__ ow, const float* __restrict__ ob) {
    __shared__ float sw2[64*65];   // transposed-padded w2 [c][j], stride 65
    __shared__ float se1[16*64];
    __shared__ float se2[16*64];
    int t = threadIdx.x;
    for (int idx = t; idx < 4096; idx += 1024) {
        int c = idx >> 6, j = idx & 63;
        sw2[c*65 + j] = __ldg(&w2[idx]);
    }
    {
        int ph = t >> 6, c = t & 63;
        int py = ph >> 2, px = ph & 3;
        float ch = (py + 0.5f)/4.0f; ch = ch - floorf(ch + 0.001f) - 0.5f;
        float cw = (px + 0.5f)/4.0f; cw = cw - floorf(cw + 0.001f) - 0.5f;
        const float cs = 0.25f;
        float s = __ldg(&b1[c]);
        s = fmaf(__ldg(&w1[c*4+0]), cs, s);
        s = fmaf(__ldg(&w1[c*4+1]), cs, s);
        s = fmaf(__ldg(&w1[c*4+2]), ch, s);
        s = fmaf(__ldg(&w1[c*4+3]), cw, s);
        se1[ph*64 + c] = fmaxf(s, 0.0f);
    }
    __syncthreads();
    {
        int ph = t >> 6, c = t & 63;
        float s = __ldg(&b2[c]);
        #pragma unroll 8
        for (int j = 0; j < 64; j++)
            s = fmaf(sw2[c*65 + j], se1[ph*64 + j], s);
        se2[ph*64 + c] = fmaxf(s, 0.0f);
    }
    __syncthreads();
    if (t < 96) {
        int ph = t / 6, which = t % 6;
        if (which < 2) {
            float s = __ldg(&ob[which]);
            for (int j = 0; j < 64; j++)
                s = fmaf(__ldg(&ow[which*64 + j]), se2[ph*64 + j], s);
            g_off[ph*2 + which] = s;
        } else {
            int e = which - 2;
            float s = __ldg(&rb[e]);
            for (int j = 0; j < 64; j++)
                s = fmaf(__ldg(&rw[e*64 + j]), se2[ph*64 + j], s);
            g_r[ph*4 + e] = 1.0f/(1.0f + expf(-s));
        }
    }
}

// ---------------- Kernel 3: build A(r), B(r) per phase ----------------
__global__ void build_ab(const float* __restrict__ wc, const float* __restrict__ we) {
    int t = blockIdx.x*blockDim.x + threadIdx.x;   // 16384 threads
    if (t < 8192) {
        int ph = t >> 9, rem = t & 511;
        int c = rem >> 3, k = rem & 7;
        float s = 0.0f;
        #pragma unroll
        for (int e = 0; e < 4; e++)
            s = fmaf(g_r[ph*4+e], __ldg(&we[(e*64 + c)*8 + k]), s);
        g_A[ph*512 + c*8 + k] = s;
    } else {
        int u = t - 8192;
        int ph = u >> 9, rem = u & 511;
        int k = rem >> 6, c = rem & 63;
        float s = 0.0f;
        #pragma unroll
        for (int e = 0; e < 4; e++)
            s = fmaf(g_r[ph*4+e], __ldg(&wc[(e*8 + k)*64 + c]), s);
        g_B[ph*512 + k*64 + c] = s;
    }
}

// ---------------- Kernel 4: fused grid-sample + expert mixing ----------------
#define PHSTR 520   // padded per-phase stride (floats)
__global__ void __launch_bounds__(128)
main_fused() {
    __shared__ float sA[4*PHSTR];
    __shared__ float sB[4*PHSTR];
    __shared__ float s_off[8];

    int p0 = blockIdx.x * 128;
    int y   = p0 >> 9;
    int py4 = y & 3;
    for (int i = threadIdx.x; i < 4*512; i += 128) {
        int phl = i >> 9, ii = i & 511;
        sA[phl*PHSTR + ii] = g_A[(py4*4 + phl)*512 + ii];
        sB[phl*PHSTR + ii] = g_B[(py4*4 + phl)*512 + ii];
    }
    if (threadIdx.x < 8) s_off[threadIdx.x] = g_off[py4*8 + threadIdx.x];
    __syncthreads();

    int p = p0 + threadIdx.x;
    int x = p & 511;
    int phl = x & 3;
    float off0 = s_off[phl*2+0];
    float off1 = s_off[phl*2+1];

    float gx = ((x + 0.5f)/4.0f - 0.5f)*2.0f/127.0f - 1.0f + off0*2.0f/127.0f;
    float gy = ((y + 0.5f)/4.0f - 0.5f)*2.0f/127.0f - 1.0f + off1*2.0f/127.0f;
    float xs = (gx + 1.0f)*0.5f*127.0f;
    float ys = (gy + 1.0f)*0.5f*127.0f;
    float x0f = floorf(xs), y0f = floorf(ys);
    float wx1 = xs - x0f, wx0 = 1.0f - wx1;
    float wy1 = ys - y0f, wy0 = 1.0f - wy1;
    int x0 = (int)x0f, y0 = (int)y0f;
    int x1 = x0 + 1, y1 = y0 + 1;
    float mx0 = ((unsigned)x0 < 128u) ? 1.0f : 0.0f;
    float mx1 = ((unsigned)x1 < 128u) ? 1.0f : 0.0f;
    float my0 = ((unsigned)y0 < 128u) ? 1.0f : 0.0f;
    float my1 = ((unsigned)y1 < 128u) ? 1.0f : 0.0f;
    float w00 = wy0*wx0*my0*mx0;
    float w01 = wy0*wx1*my0*mx1;
    float w10 = wy1*wx0*my1*mx0;
    float w11 = wy1*wx1*my1*mx1;
    int xc0 = min(max(x0,0),127), xc1 = min(max(x1,0),127);
    int yc0 = min(max(y0,0),127), yc1 = min(max(y1,0),127);
    int b00 = (yc0*128 + xc0)*16, b01 = (yc0*128 + xc1)*16;
    int b10 = (yc1*128 + xc0)*16, b11 = (yc1*128 + xc1)*16;

    const float4* F = (const float4*)g_feat;
    float4 f0[16];
    #pragma unroll
    for (int j = 0; j < 16; j++) {
        float4 v00 = F[b00+j], v01 = F[b01+j], v10 = F[b10+j], v11 = F[b11+j];
        float4 r;
        r.x = fmaf(v11.x, w11, fmaf(v10.x, w10, fmaf(v01.x, w01, v00.x*w00)));
        r.y = fmaf(v11.y, w11, fmaf(v10.y, w10, fmaf(v01.y, w01, v00.y*w00)));
        r.z = fmaf(v11.z, w11, fmaf(v10.z, w10, fmaf(v01.z, w01, v00.z*w00)));
        r.w = fmaf(v11.w, w11, fmaf(v10.w, w10, fmaf(v01.w, w01, v00.w*w00)));
        f0[j] = r;
    }

    // mid = B(ph) * fea0   (8x64)
    float mid[8];
    const float4* B4 = (const float4*)(sB + phl*PHSTR);
    #pragma unroll
    for (int k = 0; k < 8; k++) {
        float s = 0.0f;
        #pragma unroll
        for (int j = 0; j < 16; j++) {
            float4 bv = B4[k*16 + j];
            float4 fv = f0[j];
            s = fmaf(bv.x, fv.x, s);
            s = fmaf(bv.y, fv.y, s);
            s = fmaf(bv.z, fv.z, s);
            s = fmaf(bv.w, fv.w, s);
        }
        mid[k] = s;
    }

    // hidden = fea0 + A(ph) * mid   (64x8), store channel-first
    const float4* A4 = (const float4*)(sA + phl*PHSTR);
    #pragma unroll
    for (int c4 = 0; c4 < 16; c4++) {
        float4 fe = f0[c4];
        float fear[4] = {fe.x, fe.y, fe.z, fe.w};
        #pragma unroll
        for (int u = 0; u < 4; u++) {
            int c = c4*4 + u;
            float4 a0 = A4[c*2], a1 = A4[c*2+1];
            float s = fear[u];
            s = fmaf(a0.x, mid[0], s);
            s = fmaf(a0.y, mid[1], s);
            s = fmaf(a0.z, mid[2], s);
            s = fmaf(a0.w, mid[3], s);
            s = fmaf(a1.x, mid[4], s);
            s = fmaf(a1.y, mid[5], s);
            s = fmaf(a1.z, mid[6], s);
            s = fmaf(a1.w, mid[7], s);
            g_hidden[c*NPIX + p] = s;
        }
    }
}

// ---------------- Kernel 5: tail conv3x3 (64 -> 3, 512x512), smem-tiled ----------------
// tile: 64x8 outputs per block, 128 threads, 4 px/thread, 4-channel chunks
__global__ void __launch_bounds__(128)
tail_conv(const float* __restrict__ tw, const float* __restrict__ tb) {
    __shared__ float sh[4*10*72];    // [cc][row 0..9][i 0..71], i = x - X0 + 4
    __shared__ float swc[4*27];      // [cc][o][9]

    int bx = blockIdx.x & 7, by = blockIdx.x >> 3;
    int X0 = bx*64, Y0 = by*8;
    int lx = (threadIdx.x & 15)*4;
    int ly = threadIdx.x >> 4;

    float4 acc[3];
    #pragma unroll
    for (int o = 0; o < 3; o++) {
        float bo = __ldg(&tb[o]);
        acc[o] = make_float4(bo, bo, bo, bo);
    }

    for (int ch = 0; ch < 64; ch += 4) {
        __syncthreads();
        // load 4 channels x 10 rows x 72 cols (18 float4) into smem
        for (int idx = threadIdx.x; idx < 4*10*18; idx += 128) {
            int q  = idx % 18;
            int r  = (idx / 18) % 10;
            int cc = idx / 180;
            int gy  = Y0 - 1 + r;
            int gx4 = X0 - 4 + q*4;
            float4 v = make_float4(0.f, 0.f, 0.f, 0.f);
            if ((unsigned)gy < 512u && (unsigned)gx4 < 512u)
                v = *(const float4*)&g_hidden[(ch+cc)*NPIX + gy*512 + gx4];
            *(float4*)&sh[(cc*10 + r)*72 + q*4] = v;
        }
        for (int idx = threadIdx.x; idx < 108; idx += 128) {
            int cc = idx / 27, rem = idx % 27, o = rem / 9, k = rem % 9;
            swc[idx] = __ldg(&tw[(o*64 + ch + cc)*9 + k]);
        }
        __syncthreads();

        #pragma unroll
        for (int cc = 0; cc < 4; cc++) {
            float v[3][6];
            #pragma unroll
            for (int r = 0; r < 3; r++) {
                const float* row = &sh[(cc*10 + ly + r)*72];
                float4 a = *(const float4*)&row[lx];
                float4 b = *(const float4*)&row[lx+4];
                float4 c = *(const float4*)&row[lx+8];
                v[r][0]=a.w; v[r][1]=b.x; v[r][2]=b.y;
                v[r][3]=b.z; v[r][4]=b.w; v[r][5]=c.x;
            }
            #pragma unroll
            for (int o = 0; o < 3; o++) {
                const float* wp = &swc[cc*27 + o*9];
                #pragma unroll
                for (int ry = 0; ry < 3; ry++)
                    #pragma unroll
                    for (int dx = 0; dx < 3; dx++) {
                        float wv = wp[ry*3+dx];
                        acc[o].x = fmaf(v[ry][0+dx], wv, acc[o].x);
                        acc[o].y = fmaf(v[ry][1+dx], wv, acc[o].y);
                        acc[o].z = fmaf(v[ry][2+dx], wv, acc[o].z);
                        acc[o].w = fmaf(v[ry][3+dx], wv, acc[o].w);
                    }
            }
        }
    }
    int base = (Y0+ly)*512 + X0 + lx;
    #pragma unroll
    for (int o = 0; o < 3; o++)
        *(float4*)&g_pred[o*NPIX + base] = acc[o];
}

// ---------------- Kernel 6: query gather (nearest, round-half-even) ----------------
__global__ void gather_q(const float* __restrict__ coord,
                         const float* __restrict__ cell,
                         float* __restrict__ out) {
    int q = blockIdx.x*blockDim.x + threadIdx.x;
    if (q >= NQ) return;
    float cy = __ldg(&coord[q*2+0]);
    float cx = __ldg(&coord[q*2+1]);
    float ly = __ldg(&cell[q*2+0]);
    float lx = __ldg(&cell[q*2+1]);
    float gyq = fminf(fmaxf(cy - ly*0.5f + 1e-6f, -1.0f + 1e-6f), 1.0f - 1e-6f);
    float gxq = fminf(fmaxf(cx - lx*0.5f + 1e-6f, -1.0f + 1e-6f), 1.0f - 1e-6f);
    int xi = (int)rintf((gxq + 1.0f)*0.5f*511.0f);
    int yi = (int)rintf((gyq + 1.0f)*0.5f*511.0f);
    xi = min(max(xi,0),511);
    yi = min(max(yi,0),511);
    int idx = (yi << 9) + xi;
    out[q*3+0] = g_pred[idx];
    out[q*3+1] = g_pred[NPIX + idx];
    out[q*3+2] = g_pred[2*NPIX + idx];
}

extern "C" void kernel_launch(void* const* d_in, const int* in_sizes, int n_in,
                              void* d_out, int out_size) {
    const float* inp    = (const float*)d_in[0];
    const float* coord  = (const float*)d_in[1];
    const float* cell   = (const float*)d_in[2];
    const float* enc_w  = (const float*)d_in[3];
    const float* enc_b  = (const float*)d_in[4];
    const float* body_w1= (const float*)d_in[5];
    const float* body_b1= (const float*)d_in[6];
    const float* body_w2= (const float*)d_in[7];
    const float* body_b2= (const float*)d_in[8];
    const float* rout_w = (const float*)d_in[9];
    const float* rout_b = (const float*)d_in[10];
    const float* off_w  = (const float*)d_in[11];
    const float* off_b  = (const float*)d_in[12];
    const float* tail_w = (const float*)d_in[13];
    const float* tail_b = (const float*)d_in[14];
    const float* wcmp   = (const float*)d_in[15];
    const float* wexp   = (const float*)d_in[16];
    float* out = (float*)d_out;

    enc_conv<<<128, 128>>>(inp, enc_w, enc_b);
    phase_mlp<<<1, 1024>>>(body_w1, body_b1, body_w2, body_b2,
                           rout_w, rout_b, off_w, off_b);
    build_ab<<<32, 512>>>(wcmp, wexp);
    main_fused<<<2048, 128>>>();
    tail_conv<<<512, 128>>>(tail_w, tail_b);
    gather_q<<<1024, 256>>>(coord, cell, out);
}